// round 4
// baseline (speedup 1.0000x reference)
#include <cuda_runtime.h>

// Problem constants (fixed by the dataset)
#define NA 200000          // num authors
#define HID 128

// ---------------- device scratch (static, no allocation) ----------------
__device__ float g_acc[(size_t)NA * HID];  // author feature sums -> reused as author_g
__device__ float g_cnt[NA];                // per-author edge counts
__device__ float g_ac[NA];                 // author_c scalar per author
__device__ float g_B[HID * HID];           // W_author @ W_paper^T
__device__ float g_M[HID * HID];           // W_paper @ B  (collapsed operator)
__device__ float g_u1[HID];                // bias vector for count>0 rows
__device__ float g_u0[HID];                // bias vector for count==0 rows
__device__ float g_v[HID];                 // vector for author_c
__device__ float g_c1c0[2];                // scalars for author_c

// ---------------- zero accumulators ----------------
__global__ void k_zero() {
    size_t i = (size_t)blockIdx.x * blockDim.x + threadIdx.x;
    size_t stride = (size_t)gridDim.x * blockDim.x;
    float4* acc4 = reinterpret_cast<float4*>(g_acc);
    const size_t n4 = (size_t)NA * (HID / 4);
    for (size_t j = i; j < n4; j += stride) acc4[j] = make_float4(0.f, 0.f, 0.f, 0.f);
    for (size_t j = i; j < (size_t)NA; j += stride) g_cnt[j] = 0.f;
}

// ---------------- precompute step 1: B = W_author @ W_paper^T ----------------
// B[m][j] = sum_k Wa[m][k] * Wp[j][k]
__global__ void k_prep1(const float* __restrict__ Wp, const float* __restrict__ Wa) {
    __shared__ float wa[HID];
    int m = blockIdx.x;
    int j = threadIdx.x;
    wa[j] = Wa[m * HID + j];
    __syncthreads();
    float s = 0.f;
#pragma unroll 8
    for (int k = 0; k < HID; k++) s += wa[k] * Wp[j * HID + k];
    g_B[m * HID + j] = s;
}

// ---------------- precompute step 2: M = W_paper @ B, plus bias vectors ----------------
__global__ void k_prep2(const float* __restrict__ Wp, const float* __restrict__ bp,
                        const float* __restrict__ Wa, const float* __restrict__ ba) {
    int j = threadIdx.x;
    if (blockIdx.x < HID) {
        __shared__ float wp[HID];
        int i = blockIdx.x;
        wp[j] = Wp[i * HID + j];
        __syncthreads();
        float s = 0.f;
#pragma unroll 8
        for (int m = 0; m < HID; m++) s += wp[m] * g_B[m * HID + j];
        g_M[i * HID + j] = s;
    } else {
        // vector block
        __shared__ float w[HID];
        // w[m] = Wa[m,:] . b_paper
        float s = 0.f;
        for (int k = 0; k < HID; k++) s += Wa[j * HID + k] * bp[k];
        w[j] = s;
        // u0[j] = b_author . Wp[j,:]
        float u0 = 0.f;
        for (int k = 0; k < HID; k++) u0 += ba[k] * Wp[j * HID + k];
        g_u0[j] = u0;
        // u1[j] = u0[j] + sum_m b_paper[m] * B[m][j]
        float u1 = u0;
        for (int m = 0; m < HID; m++) u1 += bp[m] * g_B[m * HID + j];
        g_u1[j] = u1;
        __syncthreads();
        // v[i] = Wp[i,:] . w
        float v = 0.f;
        for (int m = 0; m < HID; m++) v += Wp[j * HID + m] * w[m];
        g_v[j] = v;
        if (j == 0) {
            float c0 = 0.f;
            for (int k = 0; k < HID; k++) c0 += ba[k] * bp[k];
            float c1 = c0;
            for (int m = 0; m < HID; m++) c1 += bp[m] * w[m];
            g_c1c0[0] = c1;
            g_c1c0[1] = c0;
        }
    }
}

// ---------------- scatter: author_sum += paper_x[pid], counts++ ----------------
// one warp per edge; lane handles 4 contiguous floats via vector reduction
__global__ void k_scatter(const float4* __restrict__ x, const int* __restrict__ aid,
                          const int* __restrict__ pid, int E) {
    int w = (int)(((size_t)blockIdx.x * blockDim.x + threadIdx.x) >> 5);
    int lane = threadIdx.x & 31;
    if (w >= E) return;
    int a = __ldg(aid + w);
    int p = __ldg(pid + w);
    float4 val = __ldg(x + (size_t)p * (HID / 4) + lane);
    float* dst = g_acc + (size_t)a * HID + lane * 4;
#if __CUDA_ARCH__ >= 900
    asm volatile("red.global.add.v4.f32 [%0], {%1, %2, %3, %4};"
                 :: "l"(dst), "f"(val.x), "f"(val.y), "f"(val.z), "f"(val.w)
                 : "memory");
#else
    atomicAdd(dst + 0, val.x);
    atomicAdd(dst + 1, val.y);
    atomicAdd(dst + 2, val.z);
    atomicAdd(dst + 3, val.w);
#endif
    if (lane == 0) atomicAdd(g_cnt + a, 1.0f);
}

// ---------------- per-author transform: g = avg_x @ M + u, c = avg_x . v + cbias ----------------
// M column is register-resident per thread (thread tid owns output column tid).
__global__ void __launch_bounds__(128, 3) k_transform(int A) {
    __shared__ float s_avg[HID];
    __shared__ float s_red[4];
    int tid = threadIdx.x;
    float Mc[HID];
#pragma unroll
    for (int k = 0; k < HID; k++) Mc[k] = g_M[k * HID + tid];
    float u1 = g_u1[tid], u0 = g_u0[tid], v = g_v[tid];
    float c1 = g_c1c0[0], c0 = g_c1c0[1];

    for (int row = blockIdx.x; row < A; row += gridDim.x) {
        float cnt = g_cnt[row];
        float inv = (cnt > 0.f) ? (1.0f / cnt) : 0.f;
        float aval = g_acc[(size_t)row * HID + tid] * inv;
        s_avg[tid] = aval;
        // author_c partial reduction
        float pp = aval * v;
#pragma unroll
        for (int o = 16; o; o >>= 1) pp += __shfl_down_sync(0xffffffffu, pp, o);
        if ((tid & 31) == 0) s_red[tid >> 5] = pp;
        __syncthreads();
        float g = (cnt > 0.f) ? u1 : u0;
#pragma unroll
        for (int k = 0; k < HID; k++) g += s_avg[k] * Mc[k];
        if (tid == 0)
            g_ac[row] = s_red[0] + s_red[1] + s_red[2] + s_red[3] + ((cnt > 0.f) ? c1 : c0);
        __syncthreads();  // all reads of s_avg/s_red done before next iteration overwrites
        g_acc[(size_t)row * HID + tid] = g;  // in-place: becomes author_g
    }
}

// ---------------- classifier: pred[e] = x[lp] . author_g[la] + author_c[la] ----------------
__global__ void k_classify(const float4* __restrict__ x, const int* __restrict__ laid,
                           const int* __restrict__ lpid, float* __restrict__ out, int L) {
    int w = (int)(((size_t)blockIdx.x * blockDim.x + threadIdx.x) >> 5);
    int lane = threadIdx.x & 31;
    if (w >= L) return;
    int a = __ldg(laid + w);
    int p = __ldg(lpid + w);
    const float4* ga4 = reinterpret_cast<const float4*>(g_acc) + (size_t)a * (HID / 4);
    float4 gv = ga4[lane];
    float4 xv = __ldg(x + (size_t)p * (HID / 4) + lane);
    float d = gv.x * xv.x + gv.y * xv.y + gv.z * xv.z + gv.w * xv.w;
#pragma unroll
    for (int o = 16; o; o >>= 1) d += __shfl_down_sync(0xffffffffu, d, o);
    if (lane == 0) out[w] = d + g_ac[a];
}

// ---------------- launch ----------------
extern "C" void kernel_launch(void* const* d_in, const int* in_sizes, int n_in,
                              void* d_out, int out_size) {
    const float* paper_x = (const float*)d_in[0];
    const int* aid  = (const int*)d_in[1];
    const int* pid  = (const int*)d_in[2];
    const int* laid = (const int*)d_in[3];
    const int* lpid = (const int*)d_in[4];
    const float* Wp = (const float*)d_in[5];
    const float* bp = (const float*)d_in[6];
    const float* Wa = (const float*)d_in[7];
    const float* ba = (const float*)d_in[8];
    float* out = (float*)d_out;

    int E = in_sizes[1];  // num edges (author_ids)
    int L = in_sizes[3];  // num label edges

    k_zero<<<2048, 256>>>();
    k_prep1<<<HID, HID>>>(Wp, Wa);
    k_prep2<<<HID + 1, HID>>>(Wp, bp, Wa, ba);
    k_scatter<<<(E + 7) / 8, 256>>>((const float4*)paper_x, aid, pid, E);
    k_transform<<<456, 128>>>(NA);
    k_classify<<<(L + 7) / 8, 256>>>((const float4*)paper_x, laid, lpid, out, L);
}

// round 6
// speedup vs baseline: 1.1507x; 1.1507x over previous
#include <cuda_runtime.h>

// Problem constants (fixed by the dataset)
#define NA 200000          // num authors
#define NP 500000          // num papers
#define NE 2000000         // num writes-edges
#define NL 500000          // num label edges
#define HID 128

// ---------------- device scratch (static, no allocation) ----------------
__device__ float g_acc[(size_t)NA * HID];  // author feature sums -> reused as author_g
__device__ float g_cnt[NA];                // per-author edge counts (float)
__device__ float g_ac[NA];                 // author_c scalar per author
__device__ float g_B[HID * HID];           // W_author @ W_paper^T
__device__ float g_M[HID * HID];           // W_paper @ B  (collapsed operator)
__device__ float g_u1[HID];                // bias vector for count>0 rows
__device__ float g_u0[HID];                // bias vector for count==0 rows
__device__ float g_v[HID];                 // vector for author_c
__device__ float g_c1c0[2];                // scalars for author_c

// edge sort (by paper)
__device__ int g_pcnt[NP];                 // paper histogram
__device__ int g_poff[NP];                 // exclusive offsets
__device__ int g_pcur[NP];                 // bump counters for reorder
__device__ int g_sa[NE];                   // author id per edge, grouped by paper

// label-edge sort (by author)
__device__ int g_lcnt[NA];
__device__ int g_loff[NA];
__device__ int g_lcur[NA];
__device__ int2 g_slab[NL];                // (paper id, original index) grouped by author

// scan temporaries (separate per scan; referenced device-side only)
__device__ int g_bsumP[512];
__device__ int g_bpreP[512];
__device__ int g_bsumL[512];
__device__ int g_bpreL[512];

// ---------------- packed f32x2 helpers ----------------
__device__ __forceinline__ unsigned long long pack2(float lo, float hi) {
    unsigned long long r;
    asm("mov.b64 %0, {%1, %2};" : "=l"(r) : "f"(lo), "f"(hi));
    return r;
}
__device__ __forceinline__ void unpack2(unsigned long long v, float& lo, float& hi) {
    asm("mov.b64 {%0, %1}, %2;" : "=f"(lo), "=f"(hi) : "l"(v));
}
#define FMA_F32X2(d, a, b, c) \
    asm("fma.rn.f32x2 %0, %1, %2, %3;" : "=l"(d) : "l"(a), "l"(b), "l"(c))

// ---------------- zero accumulators + histograms ----------------
__global__ void k_zero() {
    size_t i = (size_t)blockIdx.x * blockDim.x + threadIdx.x;
    size_t stride = (size_t)gridDim.x * blockDim.x;
    float4* acc4 = reinterpret_cast<float4*>(g_acc);
    const size_t n4 = (size_t)NA * (HID / 4);
    for (size_t j = i; j < n4; j += stride) acc4[j] = make_float4(0.f, 0.f, 0.f, 0.f);
    for (size_t j = i; j < (size_t)NA; j += stride) { g_cnt[j] = 0.f; g_lcnt[j] = 0; }
    for (size_t j = i; j < (size_t)NP; j += stride) g_pcnt[j] = 0;
}

// ---------------- histograms ----------------
__global__ void k_hist(const int* __restrict__ aid, const int* __restrict__ pid,
                       const int* __restrict__ laid) {
    int i = blockIdx.x * blockDim.x + threadIdx.x;
    int stride = gridDim.x * blockDim.x;
    for (int e = i; e < NE; e += stride) {
        atomicAdd(&g_pcnt[__ldg(pid + e)], 1);
        atomicAdd(&g_cnt[__ldg(aid + e)], 1.0f);
    }
    for (int e = i; e < NL; e += stride)
        atomicAdd(&g_lcnt[__ldg(laid + e)], 1);
}

// ---------------- two-level exclusive scan (device-side symbol access ONLY) --------
// NOTE: __device__ globals must NEVER be passed as kernel args from host code —
// the host shadow address is not the device address (silent corruption via ATS).
// Each scan stage is a thin __global__ that binds the globals inside device code.

__device__ __forceinline__ void scan1_body(const int* __restrict__ in, int* __restrict__ out,
                                           int* __restrict__ bsum, int n) {
    __shared__ int s[1024];
    int i = blockIdx.x * 1024 + threadIdx.x;
    int v = (i < n) ? in[i] : 0;
    s[threadIdx.x] = v;
    __syncthreads();
    for (int o = 1; o < 1024; o <<= 1) {
        int t = (threadIdx.x >= o) ? s[threadIdx.x - o] : 0;
        __syncthreads();
        s[threadIdx.x] += t;
        __syncthreads();
    }
    if (i < n) out[i] = s[threadIdx.x] - v;  // exclusive
    if (threadIdx.x == 1023) bsum[blockIdx.x] = s[1023];
}

__device__ __forceinline__ void scan2_body(const int* __restrict__ bsum,
                                           int* __restrict__ bpre, int nb) {
    __shared__ int s[512];
    int v = (threadIdx.x < nb) ? bsum[threadIdx.x] : 0;
    s[threadIdx.x] = v;
    __syncthreads();
    for (int o = 1; o < 512; o <<= 1) {
        int t = (threadIdx.x >= o) ? s[threadIdx.x - o] : 0;
        __syncthreads();
        s[threadIdx.x] += t;
        __syncthreads();
    }
    if (threadIdx.x < nb) bpre[threadIdx.x] = s[threadIdx.x] - v;  // exclusive
}

__device__ __forceinline__ void scan3_body(int* __restrict__ off, int* __restrict__ cur,
                                           const int* __restrict__ bpre, int n) {
    int i = blockIdx.x * 1024 + threadIdx.x;
    if (i < n) {
        int o = off[i] + bpre[blockIdx.x];
        off[i] = o;
        cur[i] = o;
    }
}

__global__ void k_scan1_p() { scan1_body(g_pcnt, g_poff, g_bsumP, NP); }
__global__ void k_scan2_p(int nb) { scan2_body(g_bsumP, g_bpreP, nb); }
__global__ void k_scan3_p() { scan3_body(g_poff, g_pcur, g_bpreP, NP); }

__global__ void k_scan1_l() { scan1_body(g_lcnt, g_loff, g_bsumL, NA); }
__global__ void k_scan2_l(int nb) { scan2_body(g_bsumL, g_bpreL, nb); }
__global__ void k_scan3_l() { scan3_body(g_loff, g_lcur, g_bpreL, NA); }

// ---------------- reorder edges by paper / label edges by author ----------------
__global__ void k_reorder_e(const int* __restrict__ aid, const int* __restrict__ pid) {
    int i = blockIdx.x * blockDim.x + threadIdx.x;
    int stride = gridDim.x * blockDim.x;
    for (int e = i; e < NE; e += stride) {
        int p = __ldg(pid + e);
        int pos = atomicAdd(&g_pcur[p], 1);
        g_sa[pos] = __ldg(aid + e);
    }
}

__global__ void k_reorder_l(const int* __restrict__ laid, const int* __restrict__ lpid) {
    int i = blockIdx.x * blockDim.x + threadIdx.x;
    int stride = gridDim.x * blockDim.x;
    for (int e = i; e < NL; e += stride) {
        int a = __ldg(laid + e);
        int pos = atomicAdd(&g_lcur[a], 1);
        g_slab[pos] = make_int2(__ldg(lpid + e), e);
    }
}

// ---------------- precompute step 1: B = W_author @ W_paper^T ----------------
__global__ void k_prep1(const float* __restrict__ Wp, const float* __restrict__ Wa) {
    __shared__ float wa[HID];
    int m = blockIdx.x;
    int j = threadIdx.x;
    wa[j] = Wa[m * HID + j];
    __syncthreads();
    float s = 0.f;
#pragma unroll 8
    for (int k = 0; k < HID; k++) s += wa[k] * Wp[j * HID + k];
    g_B[m * HID + j] = s;
}

// ---------------- precompute step 2: M = W_paper @ B, plus bias vectors ----------------
__global__ void k_prep2(const float* __restrict__ Wp, const float* __restrict__ bp,
                        const float* __restrict__ Wa, const float* __restrict__ ba) {
    int j = threadIdx.x;
    if (blockIdx.x < HID) {
        __shared__ float wp[HID];
        int i = blockIdx.x;
        wp[j] = Wp[i * HID + j];
        __syncthreads();
        float s = 0.f;
#pragma unroll 8
        for (int m = 0; m < HID; m++) s += wp[m] * g_B[m * HID + j];
        g_M[i * HID + j] = s;
    } else {
        __shared__ float w[HID];
        float s = 0.f;
        for (int k = 0; k < HID; k++) s += Wa[j * HID + k] * bp[k];
        w[j] = s;
        float u0 = 0.f;
        for (int k = 0; k < HID; k++) u0 += ba[k] * Wp[j * HID + k];
        g_u0[j] = u0;
        float u1 = u0;
        for (int m = 0; m < HID; m++) u1 += bp[m] * g_B[m * HID + j];
        g_u1[j] = u1;
        __syncthreads();
        float v = 0.f;
        for (int m = 0; m < HID; m++) v += Wp[j * HID + m] * w[m];
        g_v[j] = v;
        if (j == 0) {
            float c0 = 0.f;
            for (int k = 0; k < HID; k++) c0 += ba[k] * bp[k];
            float c1 = c0;
            for (int m = 0; m < HID; m++) c1 += bp[m] * w[m];
            g_c1c0[0] = c1;
            g_c1c0[1] = c0;
        }
    }
}

// ---------------- scatter: warp per paper, paper row read once ----------------
__global__ void k_scatter2(const float4* __restrict__ x) {
    int w = (int)(((size_t)blockIdx.x * blockDim.x + threadIdx.x) >> 5);
    int lane = threadIdx.x & 31;
    if (w >= NP) return;
    int s = g_poff[w];
    int e = (w + 1 < NP) ? g_poff[w + 1] : NE;
    if (s == e) return;
    float4 val = __ldg(x + (size_t)w * (HID / 4) + lane);
    for (int i = s; i < e; i++) {
        int a = __ldg(g_sa + i);  // warp-uniform broadcast
        float* dst = g_acc + (size_t)a * HID + lane * 4;
        asm volatile("red.global.add.v4.f32 [%0], {%1, %2, %3, %4};"
                     :: "l"(dst), "f"(val.x), "f"(val.y), "f"(val.z), "f"(val.w)
                     : "memory");
    }
}

// ---------------- per-author transform with packed f32x2 FMA ----------------
__global__ void __launch_bounds__(128, 3) k_transform(int A) {
    __shared__ __align__(16) float s_avg[HID];
    __shared__ float s_red[4];
    int tid = threadIdx.x;

    // Mc[kp] holds (M[2kp][tid], M[2kp+1][tid]) packed as f32x2
    unsigned long long Mc[HID / 2];
#pragma unroll
    for (int kp = 0; kp < HID / 2; kp++)
        Mc[kp] = pack2(g_M[(2 * kp) * HID + tid], g_M[(2 * kp + 1) * HID + tid]);

    float u1 = g_u1[tid], u0 = g_u0[tid], v = g_v[tid];
    float c1 = g_c1c0[0], c0 = g_c1c0[1];

    for (int row = blockIdx.x; row < A; row += gridDim.x) {
        float cnt = g_cnt[row];
        float inv = (cnt > 0.f) ? (1.0f / cnt) : 0.f;
        float aval = g_acc[(size_t)row * HID + tid] * inv;
        s_avg[tid] = aval;
        // author_c partial reduction
        float pp = aval * v;
#pragma unroll
        for (int o = 16; o; o >>= 1) pp += __shfl_down_sync(0xffffffffu, pp, o);
        if ((tid & 31) == 0) s_red[tid >> 5] = pp;
        __syncthreads();

        unsigned long long acc2 = pack2(0.f, 0.f);
        const unsigned long long* avg2 = reinterpret_cast<const unsigned long long*>(s_avg);
#pragma unroll
        for (int kp = 0; kp < HID / 2; kp++)
            FMA_F32X2(acc2, avg2[kp], Mc[kp], acc2);
        float alo, ahi;
        unpack2(acc2, alo, ahi);
        float g = alo + ahi + ((cnt > 0.f) ? u1 : u0);

        if (tid == 0)
            g_ac[row] = s_red[0] + s_red[1] + s_red[2] + s_red[3] + ((cnt > 0.f) ? c1 : c0);
        __syncthreads();  // reads of s_avg/s_red complete before next overwrite
        g_acc[(size_t)row * HID + tid] = g;  // in-place: becomes author_g
    }
}

// ---------------- classifier: warp per author, author_g row read once ----------------
__global__ void k_classify2(const float4* __restrict__ x, float* __restrict__ out) {
    int w = (int)(((size_t)blockIdx.x * blockDim.x + threadIdx.x) >> 5);
    int lane = threadIdx.x & 31;
    if (w >= NA) return;
    int s = g_loff[w];
    int e = (w + 1 < NA) ? g_loff[w + 1] : NL;
    if (s == e) return;
    const float4* ga4 = reinterpret_cast<const float4*>(g_acc) + (size_t)w * (HID / 4);
    float4 gv = ga4[lane];
    float ac = g_ac[w];
    for (int i = s; i < e; i++) {
        int2 pe = __ldg(g_slab + i);  // (paper, orig index), warp-uniform broadcast
        float4 xv = __ldg(x + (size_t)pe.x * (HID / 4) + lane);
        float d = gv.x * xv.x + gv.y * xv.y + gv.z * xv.z + gv.w * xv.w;
#pragma unroll
        for (int o = 16; o; o >>= 1) d += __shfl_down_sync(0xffffffffu, d, o);
        if (lane == 0) out[pe.y] = d + ac;
    }
}

// ---------------- launch ----------------
extern "C" void kernel_launch(void* const* d_in, const int* in_sizes, int n_in,
                              void* d_out, int out_size) {
    const float* paper_x = (const float*)d_in[0];
    const int* aid  = (const int*)d_in[1];
    const int* pid  = (const int*)d_in[2];
    const int* laid = (const int*)d_in[3];
    const int* lpid = (const int*)d_in[4];
    const float* Wp = (const float*)d_in[5];
    const float* bp = (const float*)d_in[6];
    const float* Wa = (const float*)d_in[7];
    const float* ba = (const float*)d_in[8];
    float* out = (float*)d_out;

    // zero + histograms
    k_zero<<<2048, 256>>>();
    k_hist<<<2048, 256>>>(aid, pid, laid);

    // scan paper histogram (NP = 500000 -> 489 blocks)
    {
        int nb = (NP + 1023) / 1024;
        k_scan1_p<<<nb, 1024>>>();
        k_scan2_p<<<1, 512>>>(nb);
        k_scan3_p<<<nb, 1024>>>();
    }
    // scan label-author histogram (NA = 200000 -> 196 blocks)
    {
        int nb = (NA + 1023) / 1024;
        k_scan1_l<<<nb, 1024>>>();
        k_scan2_l<<<1, 512>>>(nb);
        k_scan3_l<<<nb, 1024>>>();
    }

    // reorders
    k_reorder_e<<<2048, 256>>>(aid, pid);
    k_reorder_l<<<1024, 256>>>(laid, lpid);

    // collapsed-operator precompute (independent of sorts)
    k_prep1<<<HID, HID>>>(Wp, Wa);
    k_prep2<<<HID + 1, HID>>>(Wp, bp, Wa, ba);

    // main phases
    k_scatter2<<<(NP + 7) / 8, 256>>>((const float4*)paper_x);
    k_transform<<<456, 128>>>(NA);
    k_classify2<<<(NA + 7) / 8, 256>>>((const float4*)paper_x, out);
}

// round 7
// speedup vs baseline: 1.6779x; 1.4581x over previous
#include <cuda_runtime.h>

// Problem constants (fixed by the dataset)
#define NA 200000          // num authors
#define NP 500000          // num papers
#define NE 2000000         // num writes-edges
#define NL 500000          // num label edges
#define HID 128

// ---------------- device scratch (static, no allocation) ----------------
__device__ float g_acc[(size_t)NA * HID];  // author avg-x -> reused as author_g
__device__ float g_ac[NA];                 // author_c scalar per author
__device__ float g_B[HID * HID];           // W_author @ W_paper^T
__device__ float g_M[HID * HID];           // W_paper @ B  (collapsed operator)
__device__ float g_u1[HID];                // bias vector for count>0 rows
__device__ float g_u0[HID];                // bias vector for count==0 rows
__device__ float g_v[HID];                 // vector for author_c
__device__ float g_c1c0[2];                // scalars for author_c

// edge sort (by author)
__device__ int g_acnt[NA];                 // author edge histogram
__device__ int g_aoff[NA];                 // exclusive offsets
__device__ int g_acur[NA];                 // bump counters
__device__ int g_sp[NE];                   // paper id per edge, grouped by author

// label-edge sort (by author)
__device__ int g_lcnt[NA];
__device__ int g_loff[NA];
__device__ int g_lcur[NA];
__device__ int2 g_slab[NL];                // (paper id, original index) grouped by author

// scan temporaries (device-side access only!)
__device__ int g_bsA[512];
__device__ int g_bpA[512];
__device__ int g_bsL[512];
__device__ int g_bpL[512];

// ---------------- packed f32x2 helpers ----------------
__device__ __forceinline__ unsigned long long pack2(float lo, float hi) {
    unsigned long long r;
    asm("mov.b64 %0, {%1, %2};" : "=l"(r) : "f"(lo), "f"(hi));
    return r;
}
__device__ __forceinline__ void unpack2(unsigned long long v, float& lo, float& hi) {
    asm("mov.b64 {%0, %1}, %2;" : "=f"(lo), "=f"(hi) : "l"(v));
}
#define FMA_F32X2(d, a, b, c) \
    asm("fma.rn.f32x2 %0, %1, %2, %3;" : "=l"(d) : "l"(a), "l"(b), "l"(c))

// ---------------- zero histograms (only small arrays now) ----------------
__global__ void k_zero() {
    int i = blockIdx.x * blockDim.x + threadIdx.x;
    int stride = gridDim.x * blockDim.x;
    for (int j = i; j < NA; j += stride) { g_acnt[j] = 0; g_lcnt[j] = 0; }
}

// ---------------- histograms: author edge counts + label author counts ----------------
__global__ void k_hist(const int* __restrict__ aid, const int* __restrict__ laid) {
    int i = blockIdx.x * blockDim.x + threadIdx.x;
    int stride = gridDim.x * blockDim.x;
    for (int e = i; e < NE; e += stride)
        atomicAdd(&g_acnt[__ldg(aid + e)], 1);
    for (int e = i; e < NL; e += stride)
        atomicAdd(&g_lcnt[__ldg(laid + e)], 1);
}

// ---------------- two-level exclusive scan (device-side symbol binding ONLY) --------
// __device__ globals must never be passed as kernel args from host code (host
// shadow address != device address; ATS makes the bug silent).
__device__ __forceinline__ void scan1_body(const int* __restrict__ in, int* __restrict__ out,
                                           int* __restrict__ bsum, int n) {
    __shared__ int s[1024];
    int i = blockIdx.x * 1024 + threadIdx.x;
    int v = (i < n) ? in[i] : 0;
    s[threadIdx.x] = v;
    __syncthreads();
    for (int o = 1; o < 1024; o <<= 1) {
        int t = (threadIdx.x >= o) ? s[threadIdx.x - o] : 0;
        __syncthreads();
        s[threadIdx.x] += t;
        __syncthreads();
    }
    if (i < n) out[i] = s[threadIdx.x] - v;  // exclusive
    if (threadIdx.x == 1023) bsum[blockIdx.x] = s[1023];
}

__device__ __forceinline__ void scan2_body(const int* __restrict__ bsum,
                                           int* __restrict__ bpre, int nb) {
    __shared__ int s[512];
    int v = (threadIdx.x < nb) ? bsum[threadIdx.x] : 0;
    s[threadIdx.x] = v;
    __syncthreads();
    for (int o = 1; o < 512; o <<= 1) {
        int t = (threadIdx.x >= o) ? s[threadIdx.x - o] : 0;
        __syncthreads();
        s[threadIdx.x] += t;
        __syncthreads();
    }
    if (threadIdx.x < nb) bpre[threadIdx.x] = s[threadIdx.x] - v;  // exclusive
}

__device__ __forceinline__ void scan3_body(int* __restrict__ off, int* __restrict__ cur,
                                           const int* __restrict__ bpre, int n) {
    int i = blockIdx.x * 1024 + threadIdx.x;
    if (i < n) {
        int o = off[i] + bpre[blockIdx.x];
        off[i] = o;
        cur[i] = o;
    }
}

__global__ void k_scan1_a() { scan1_body(g_acnt, g_aoff, g_bsA, NA); }
__global__ void k_scan2_a(int nb) { scan2_body(g_bsA, g_bpA, nb); }
__global__ void k_scan3_a() { scan3_body(g_aoff, g_acur, g_bpA, NA); }

__global__ void k_scan1_l() { scan1_body(g_lcnt, g_loff, g_bsL, NA); }
__global__ void k_scan2_l(int nb) { scan2_body(g_bsL, g_bpL, nb); }
__global__ void k_scan3_l() { scan3_body(g_loff, g_lcur, g_bpL, NA); }

// ---------------- reorder edges by author / label edges by author ----------------
__global__ void k_reorder_e(const int* __restrict__ aid, const int* __restrict__ pid) {
    int i = blockIdx.x * blockDim.x + threadIdx.x;
    int stride = gridDim.x * blockDim.x;
    for (int e = i; e < NE; e += stride) {
        int a = __ldg(aid + e);
        int pos = atomicAdd(&g_acur[a], 1);
        g_sp[pos] = __ldg(pid + e);
    }
}

__global__ void k_reorder_l(const int* __restrict__ laid, const int* __restrict__ lpid) {
    int i = blockIdx.x * blockDim.x + threadIdx.x;
    int stride = gridDim.x * blockDim.x;
    for (int e = i; e < NL; e += stride) {
        int a = __ldg(laid + e);
        int pos = atomicAdd(&g_lcur[a], 1);
        g_slab[pos] = make_int2(__ldg(lpid + e), e);
    }
}

// ---------------- precompute step 1: B = W_author @ W_paper^T ----------------
__global__ void k_prep1(const float* __restrict__ Wp, const float* __restrict__ Wa) {
    __shared__ float wa[HID];
    int m = blockIdx.x;
    int j = threadIdx.x;
    wa[j] = Wa[m * HID + j];
    __syncthreads();
    float s = 0.f;
#pragma unroll 8
    for (int k = 0; k < HID; k++) s += wa[k] * Wp[j * HID + k];
    g_B[m * HID + j] = s;
}

// ---------------- precompute step 2: M = W_paper @ B, plus bias vectors ----------------
__global__ void k_prep2(const float* __restrict__ Wp, const float* __restrict__ bp,
                        const float* __restrict__ Wa, const float* __restrict__ ba) {
    int j = threadIdx.x;
    if (blockIdx.x < HID) {
        __shared__ float wp[HID];
        int i = blockIdx.x;
        wp[j] = Wp[i * HID + j];
        __syncthreads();
        float s = 0.f;
#pragma unroll 8
        for (int m = 0; m < HID; m++) s += wp[m] * g_B[m * HID + j];
        g_M[i * HID + j] = s;
    } else {
        __shared__ float w[HID];
        float s = 0.f;
        for (int k = 0; k < HID; k++) s += Wa[j * HID + k] * bp[k];
        w[j] = s;
        float u0 = 0.f;
        for (int k = 0; k < HID; k++) u0 += ba[k] * Wp[j * HID + k];
        g_u0[j] = u0;
        float u1 = u0;
        for (int m = 0; m < HID; m++) u1 += bp[m] * g_B[m * HID + j];
        g_u1[j] = u1;
        __syncthreads();
        float v = 0.f;
        for (int m = 0; m < HID; m++) v += Wp[j * HID + m] * w[m];
        g_v[j] = v;
        if (j == 0) {
            float c0 = 0.f;
            for (int k = 0; k < HID; k++) c0 += ba[k] * bp[k];
            float c1 = c0;
            for (int m = 0; m < HID; m++) c1 += bp[m] * w[m];
            g_c1c0[0] = c1;
            g_c1c0[1] = c0;
        }
    }
}

// ---------------- gather-average: warp per author, register accumulation ----------------
// Replaces zeroing + atomic reductions entirely. 4-deep unroll for MLP.
__global__ void k_gather_avg(const float4* __restrict__ x) {
    int w = (int)(((size_t)blockIdx.x * blockDim.x + threadIdx.x) >> 5);
    int lane = threadIdx.x & 31;
    if (w >= NA) return;
    int s = g_aoff[w];
    int e = (w + 1 < NA) ? g_aoff[w + 1] : NE;

    float4 a0 = make_float4(0.f, 0.f, 0.f, 0.f);
    float4 a1 = make_float4(0.f, 0.f, 0.f, 0.f);
    int i = s;
    for (; i + 4 <= e; i += 4) {
        int p0 = __ldg(g_sp + i + 0);
        int p1 = __ldg(g_sp + i + 1);
        int p2 = __ldg(g_sp + i + 2);
        int p3 = __ldg(g_sp + i + 3);
        float4 v0 = __ldg(x + (size_t)p0 * (HID / 4) + lane);
        float4 v1 = __ldg(x + (size_t)p1 * (HID / 4) + lane);
        float4 v2 = __ldg(x + (size_t)p2 * (HID / 4) + lane);
        float4 v3 = __ldg(x + (size_t)p3 * (HID / 4) + lane);
        a0.x += v0.x + v2.x; a0.y += v0.y + v2.y; a0.z += v0.z + v2.z; a0.w += v0.w + v2.w;
        a1.x += v1.x + v3.x; a1.y += v1.y + v3.y; a1.z += v1.z + v3.z; a1.w += v1.w + v3.w;
    }
    for (; i < e; i++) {
        int p = __ldg(g_sp + i);
        float4 v = __ldg(x + (size_t)p * (HID / 4) + lane);
        a0.x += v.x; a0.y += v.y; a0.z += v.z; a0.w += v.w;
    }
    float inv = (e > s) ? (1.0f / (float)(e - s)) : 0.f;
    float4 acc;
    acc.x = (a0.x + a1.x) * inv;
    acc.y = (a0.y + a1.y) * inv;
    acc.z = (a0.z + a1.z) * inv;
    acc.w = (a0.w + a1.w) * inv;
    reinterpret_cast<float4*>(g_acc)[(size_t)w * (HID / 4) + lane] = acc;
}

// ---------------- per-author transform with packed f32x2 FMA ----------------
// Reads pre-averaged rows; software-prefetches the next row to hide DRAM latency.
__global__ void __launch_bounds__(128, 3) k_transform(int A) {
    __shared__ __align__(16) float s_avg[HID];
    __shared__ float s_red[4];
    int tid = threadIdx.x;

    // Mc[kp] holds (M[2kp][tid], M[2kp+1][tid]) packed as f32x2
    unsigned long long Mc[HID / 2];
#pragma unroll
    for (int kp = 0; kp < HID / 2; kp++)
        Mc[kp] = pack2(g_M[(2 * kp) * HID + tid], g_M[(2 * kp + 1) * HID + tid]);

    float u1 = g_u1[tid], u0 = g_u0[tid], v = g_v[tid];
    float c1 = g_c1c0[0], c0 = g_c1c0[1];

    int row = blockIdx.x;
    float aval_next = (row < A) ? g_acc[(size_t)row * HID + tid] : 0.f;
    for (; row < A; row += gridDim.x) {
        float aval = aval_next;
        int nrow = row + gridDim.x;
        if (nrow < A) aval_next = g_acc[(size_t)nrow * HID + tid];  // prefetch

        int rs = g_aoff[row];
        int re = (row + 1 < NA) ? g_aoff[row + 1] : NE;
        bool has = (re > rs);

        s_avg[tid] = aval;
        float pp = aval * v;
#pragma unroll
        for (int o = 16; o; o >>= 1) pp += __shfl_down_sync(0xffffffffu, pp, o);
        if ((tid & 31) == 0) s_red[tid >> 5] = pp;
        __syncthreads();

        unsigned long long acc2 = pack2(0.f, 0.f);
        const unsigned long long* avg2 = reinterpret_cast<const unsigned long long*>(s_avg);
#pragma unroll
        for (int kp = 0; kp < HID / 2; kp++)
            FMA_F32X2(acc2, avg2[kp], Mc[kp], acc2);
        float alo, ahi;
        unpack2(acc2, alo, ahi);
        float g = alo + ahi + (has ? u1 : u0);

        if (tid == 0)
            g_ac[row] = s_red[0] + s_red[1] + s_red[2] + s_red[3] + (has ? c1 : c0);
        __syncthreads();  // reads of s_avg/s_red complete before next overwrite
        g_acc[(size_t)row * HID + tid] = g;  // in-place: becomes author_g
    }
}

// ---------------- classifier: warp per author, 2-wide unroll for MLP ----------------
__global__ void k_classify2(const float4* __restrict__ x, float* __restrict__ out) {
    int w = (int)(((size_t)blockIdx.x * blockDim.x + threadIdx.x) >> 5);
    int lane = threadIdx.x & 31;
    if (w >= NA) return;
    int s = g_loff[w];
    int e = (w + 1 < NA) ? g_loff[w + 1] : NL;
    if (s == e) return;
    const float4* ga4 = reinterpret_cast<const float4*>(g_acc) + (size_t)w * (HID / 4);
    float4 gv = ga4[lane];
    float ac = g_ac[w];
    int i = s;
    for (; i + 2 <= e; i += 2) {
        int2 pe0 = __ldg(g_slab + i);
        int2 pe1 = __ldg(g_slab + i + 1);
        float4 x0 = __ldg(x + (size_t)pe0.x * (HID / 4) + lane);
        float4 x1 = __ldg(x + (size_t)pe1.x * (HID / 4) + lane);
        float d0 = gv.x * x0.x + gv.y * x0.y + gv.z * x0.z + gv.w * x0.w;
        float d1 = gv.x * x1.x + gv.y * x1.y + gv.z * x1.z + gv.w * x1.w;
#pragma unroll
        for (int o = 16; o; o >>= 1) {
            d0 += __shfl_down_sync(0xffffffffu, d0, o);
            d1 += __shfl_down_sync(0xffffffffu, d1, o);
        }
        if (lane == 0) { out[pe0.y] = d0 + ac; out[pe1.y] = d1 + ac; }
    }
    if (i < e) {
        int2 pe = __ldg(g_slab + i);
        float4 xv = __ldg(x + (size_t)pe.x * (HID / 4) + lane);
        float d = gv.x * xv.x + gv.y * xv.y + gv.z * xv.z + gv.w * xv.w;
#pragma unroll
        for (int o = 16; o; o >>= 1) d += __shfl_down_sync(0xffffffffu, d, o);
        if (lane == 0) out[pe.y] = d + ac;
    }
}

// ---------------- launch ----------------
extern "C" void kernel_launch(void* const* d_in, const int* in_sizes, int n_in,
                              void* d_out, int out_size) {
    const float* paper_x = (const float*)d_in[0];
    const int* aid  = (const int*)d_in[1];
    const int* pid  = (const int*)d_in[2];
    const int* laid = (const int*)d_in[3];
    const int* lpid = (const int*)d_in[4];
    const float* Wp = (const float*)d_in[5];
    const float* bp = (const float*)d_in[6];
    const float* Wa = (const float*)d_in[7];
    const float* ba = (const float*)d_in[8];
    float* out = (float*)d_out;

    k_zero<<<512, 256>>>();
    k_hist<<<2048, 256>>>(aid, laid);

    // scans (NA = 200000 -> 196 blocks)
    {
        int nb = (NA + 1023) / 1024;
        k_scan1_a<<<nb, 1024>>>();
        k_scan2_a<<<1, 512>>>(nb);
        k_scan3_a<<<nb, 1024>>>();
        k_scan1_l<<<nb, 1024>>>();
        k_scan2_l<<<1, 512>>>(nb);
        k_scan3_l<<<nb, 1024>>>();
    }

    // reorders
    k_reorder_e<<<2048, 256>>>(aid, pid);
    k_reorder_l<<<1024, 256>>>(laid, lpid);

    // collapsed-operator precompute
    k_prep1<<<HID, HID>>>(Wp, Wa);
    k_prep2<<<HID + 1, HID>>>(Wp, bp, Wa, ba);

    // main phases
    k_gather_avg<<<(NA + 7) / 8, 256>>>((const float4*)paper_x);
    k_transform<<<456, 128>>>(NA);
    k_classify2<<<(NA + 7) / 8, 256>>>((const float4*)paper_x, out);
}